// round 5
// baseline (speedup 1.0000x reference)
#include <cuda_runtime.h>
#include <cstdint>

#define SEQ     256
#define BATCH   512
#define IN_DIM  256
#define HDIM    8
#define DIN     264          // IN_DIM + HDIM
#define NROWS   (SEQ * BATCH)

// Scratch: pre-activations, bias folded in.
// Layout: zx[(t*BATCH + b)*32 + q*4 + g]   (gate-minor so recur does 1 LDG.128)
// Padded by one extra t-row so the recur prefetch never reads OOB.
__device__ __align__(16) float g_zx[(size_t)(NROWS + BATCH) * 32];

typedef unsigned long long ull;

__device__ __forceinline__ void ffma2(ull &d, ull a, ull b) {
    asm("fma.rn.f32x2 %0, %1, %2, %0;" : "+l"(d) : "l"(a), "l"(b));
}
__device__ __forceinline__ ull pack2(float lo, float hi) {
    ull r; asm("mov.b64 %0, {%1, %2};" : "=l"(r) : "f"(lo), "f"(hi)); return r;
}
__device__ __forceinline__ void unpack2(float &lo, float &hi, ull v) {
    asm("mov.b64 {%0, %1}, %2;" : "=f"(lo), "=f"(hi) : "l"(v));
}
__device__ __forceinline__ float tanh_approx(float x) {
    float y; asm("tanh.approx.f32 %0, %1;" : "=f"(y) : "f"(x)); return y;
}
__device__ __forceinline__ void cpasync16(void* dst, const void* src) {
    unsigned ds = (unsigned)__cvta_generic_to_shared(dst);
    asm volatile("cp.async.cg.shared.global [%0], [%1], 16;" :: "r"(ds), "l"(src));
}
__device__ __forceinline__ void cp_commit() { asm volatile("cp.async.commit_group;"); }
template <int N> __device__ __forceinline__ void cp_wait() {
    asm volatile("cp.async.wait_group %0;" :: "n"(N));
}

// ---------------------------------------------------------------------------
// Kernel A: zx = x @ Wx.T + b. Block 256 thr, 128 rows, grid 1024.
// k split across half-warps: kh = lane>>4 picks 16-wide k-half; lane covers
// outputs oA=lane&15 and oB=oA+16. Per chunk: 64 x-LDS + 8 w-LDS + 256 FFMA2
// -> FMA-pipe bound. Cross-half sum: each lane SENDS the accumulator it does
// NOT store (lane<16 sends accB, lane>=16 sends accA) — the partner needs the
// same-output other-half, which is exactly that register.
// 3-stage cp.async x pipeline, ONE __syncthreads per chunk.
// Dynamic smem: w_s (32KB) + 3 x-buffers (48KB) = 80KB.
// ---------------------------------------------------------------------------
#define KCH    32
#define NCHUNK 8
#define GEMM_SMEM_FLOATS (32 * 256 + 3 * 128 * 32)
#define GEMM_SMEM_BYTES  (GEMM_SMEM_FLOATS * 4)

__global__ void __launch_bounds__(256)
qlstm_gemm(const float* __restrict__ x,
           const float* __restrict__ Wf, const float* __restrict__ bf,
           const float* __restrict__ Wi, const float* __restrict__ bi,
           const float* __restrict__ Wu, const float* __restrict__ bu,
           const float* __restrict__ Wo, const float* __restrict__ bo)
{
    extern __shared__ __align__(16) float smem[];
    float* w_s = smem;                      // 32 rows x 256 floats (swizzled 16B slots)
    float* xs[3] = { smem + 8192, smem + 8192 + 4096, smem + 8192 + 2 * 4096 };

    const unsigned FULL = 0xFFFFFFFFu;
    const int tid  = threadIdx.x;
    const int lane = tid & 31, warp = tid >> 5;
    const int kh   = lane >> 4;             // k-half
    const int oA   = lane & 15, oB = oA + 16;
    const int row0  = blockIdx.x * 128;
    const int wrow0 = warp * 16;

    // Stage W x-part: 32 rows x 64 16B-slots = 2048, 8 per thread, swizzled.
    #pragma unroll
    for (int i = 0; i < 8; i++) {
        int idx = tid + 256 * i;
        int o = idx >> 6, s = idx & 63;
        int sw = (s & ~7) | ((s & 7) ^ (o & 7));
        int g = o >> 3, q = o & 7;
        const float* base = (g == 0 ? Wf : (g == 1 ? Wi : (g == 2 ? Wu : Wo)));
        cpasync16(&w_s[o * 256 + sw * 4], base + q * DIN + s * 4);
    }

    auto load_x = [&](int kc, int buf) {
        #pragma unroll
        for (int i = 0; i < 4; i++) {
            int idx = tid + 256 * i;        // 1024 slots: 128 rows x 8 slots
            int r = idx >> 3, s = idx & 7;
            cpasync16(&xs[buf][r * 32 + s * 4],
                      x + (size_t)(row0 + r) * IN_DIM + kc * KCH + s * 4);
        }
    };

    load_x(0, 0); cp_commit();              // group 0: {W, x0}
    load_x(1, 1); cp_commit();              // group 1: {x1}

    ull accA[16], accB[16];
    #pragma unroll
    for (int r = 0; r < 16; r++) { accA[r] = 0ULL; accB[r] = 0ULL; }

    #pragma unroll 1
    for (int kc = 0; kc < NCHUNK; kc++) {
        cp_wait<1>();                       // chunk kc (and W) arrived for this thread
        __syncthreads();                    // ...visible to all; prev compute done
        if (kc + 2 < NCHUNK) { load_x(kc + 2, (kc + 2) % 3); cp_commit(); }

        // this lane's weights: both outputs, its 16-wide k-half
        ull wA[8], wB[8];
        #pragma unroll
        for (int j = 0; j < 4; j++) {
            int s  = kc * 8 + kh * 4 + j;
            int sw = (s & ~7) | ((s & 7) ^ (lane & 7));   // oA&7 == oB&7 == lane&7
            ulonglong2 a = *reinterpret_cast<const ulonglong2*>(&w_s[oA * 256 + sw * 4]);
            ulonglong2 c = *reinterpret_cast<const ulonglong2*>(&w_s[oB * 256 + sw * 4]);
            wA[2*j] = a.x; wA[2*j+1] = a.y;
            wB[2*j] = c.x; wB[2*j+1] = c.y;
        }

        const float* xb = xs[kc % 3];
        #pragma unroll
        for (int r = 0; r < 16; r++) {
            const float* xrow = xb + (wrow0 + r) * 32 + kh * 16;
            #pragma unroll
            for (int j = 0; j < 4; j++) {
                ulonglong2 xv = *reinterpret_cast<const ulonglong2*>(xrow + j * 4);
                ffma2(accA[r], xv.x, wA[2*j]); ffma2(accA[r], xv.y, wA[2*j+1]);
                ffma2(accB[r], xv.x, wB[2*j]); ffma2(accB[r], xv.y, wB[2*j+1]);
            }
        }
    }

    // lane stores output o = lane. Keep the matching accumulator; SEND the
    // other one (that's the partner's same-output, other-k-half part).
    const int g = lane >> 3, q = lane & 7;
    const float bias = (g == 0 ? bf : (g == 1 ? bi : (g == 2 ? bu : bo)))[q];
    const int col = q * 4 + g;              // gate-minor layout for recur

    #pragma unroll
    for (int r = 0; r < 16; r++) {
        ull mine = (lane < 16) ? accA[r] : accB[r];   // output == lane, my k-half
        ull send = (lane < 16) ? accB[r] : accA[r];   // partner's output, my k-half
        ull othr = __shfl_xor_sync(FULL, send, 16);   // output == lane, other k-half
        float a0, a1, b0, b1;
        unpack2(a0, a1, mine); unpack2(b0, b1, othr);
        g_zx[(size_t)(row0 + wrow0 + r) * 32 + col] = (a0 + a1) + (b0 + b1) + bias;
    }
}

// ---------------------------------------------------------------------------
// Kernel B: recurrence. One warp = FOUR batch elements; lane = (b_sub, q).
// Each lane computes all 4 gates for its qubit, so each shfl instruction
// serves 4 batch elements: 5 shfl/elem/step (was 15) and no gate gather.
// Dots use packed fma.rn.f32x2 on (f,i) and (u,o) pairs. Sigmoid's x0.5 is
// folded into the q==0 cos-prefactor (scales every inclusive prefix).
// ---------------------------------------------------------------------------
__global__ void __launch_bounds__(32)
qlstm_recur(const float* __restrict__ Wf, const float* __restrict__ Wi,
            const float* __restrict__ Wu, const float* __restrict__ Wo,
            const float* __restrict__ pf, const float* __restrict__ pi_,
            const float* __restrict__ pu, const float* __restrict__ po,
            float* __restrict__ out)
{
    const unsigned FULL = 0xFFFFFFFFu;
    const int lane = threadIdx.x & 31;
    const int bsub = lane >> 3, q = lane & 7;
    const int b = blockIdx.x * 4 + bsub;

    // recurrent weights for this qubit, packed (f,i) and (u,o)
    ull wfi[8], wuo[8];
    #pragma unroll
    for (int j = 0; j < 8; j++) {
        wfi[j] = pack2(Wf[q * DIN + IN_DIM + j], Wi[q * DIN + IN_DIM + j]);
        wuo[j] = pack2(Wu[q * DIN + IN_DIM + j], Wo[q * DIN + IN_DIM + j]);
    }
    float cthf = __cosf(pf[q]), cthi = __cosf(pi_[q]);
    float cthu = __cosf(pu[q]), ctho = __cosf(po[q]);
    if (q == 0) { cthf *= 0.5f; cthi *= 0.5f; ctho *= 0.5f; }   // sigmoid 0.5x, folded

    const bool p1 = (q >= 1), p2 = (q >= 2), p4 = (q >= 4);

    const float* zrow = g_zx + (size_t)b * 32 + q * 4;
    const size_t zstr = (size_t)BATCH * 32;

    float* sp     = out + (size_t)b * HDIM + q;
    float* hx_out = out + (size_t)SEQ * BATCH * HDIM;
    float* cx_out = hx_out + (size_t)BATCH * HDIM;

    ull h2[8];
    #pragma unroll
    for (int j = 0; j < 8; j++) h2[j] = 0ULL;
    float c = 0.f, hnew = 0.f;

    ulonglong2 z2 = *reinterpret_cast<const ulonglong2*>(zrow);

    #pragma unroll 2
    for (int t = 0; t < SEQ; t++) {
        // prefetch next step (padded array -> always in-bounds)
        ulonglong2 zn = *reinterpret_cast<const ulonglong2*>(zrow + (size_t)(t + 1) * zstr);

        // z for all 4 gates: packed dots over the 8 recurrent weights
        ull zfi = z2.x, zuo = z2.y;
        #pragma unroll
        for (int j = 0; j < 8; j++) { ffma2(zfi, h2[j], wfi[j]); ffma2(zuo, h2[j], wuo[j]); }
        float zf, zi, zu, zo;
        unpack2(zf, zi, zfi); unpack2(zu, zo, zuo);

        float cf = __cosf(zf) * cthf, ci = __cosf(zi) * cthi;
        float cu = __cosf(zu) * cthu, co = __cosf(zo) * ctho;

        // 8-wide inclusive prefix product, 4 gates per shfl level
        {
            float vf = __shfl_up_sync(FULL, cf, 1, 8);
            float vi = __shfl_up_sync(FULL, ci, 1, 8);
            float vu = __shfl_up_sync(FULL, cu, 1, 8);
            float vo = __shfl_up_sync(FULL, co, 1, 8);
            cf *= p1 ? vf : 1.f; ci *= p1 ? vi : 1.f; cu *= p1 ? vu : 1.f; co *= p1 ? vo : 1.f;
        }
        {
            float vf = __shfl_up_sync(FULL, cf, 2, 8);
            float vi = __shfl_up_sync(FULL, ci, 2, 8);
            float vu = __shfl_up_sync(FULL, cu, 2, 8);
            float vo = __shfl_up_sync(FULL, co, 2, 8);
            cf *= p2 ? vf : 1.f; ci *= p2 ? vi : 1.f; cu *= p2 ? vu : 1.f; co *= p2 ? vo : 1.f;
        }
        {
            float vf = __shfl_up_sync(FULL, cf, 4, 8);
            float vi = __shfl_up_sync(FULL, ci, 4, 8);
            float vu = __shfl_up_sync(FULL, cu, 4, 8);
            float vo = __shfl_up_sync(FULL, co, 4, 8);
            cf *= p4 ? vf : 1.f; ci *= p4 ? vi : 1.f; cu *= p4 ? vu : 1.f; co *= p4 ? vo : 1.f;
        }

        // activations: sigma(x) = 0.5*tanh(0.5x)+0.5 (0.5x already folded); u: tanh
        float af = fmaf(0.5f, tanh_approx(cf), 0.5f);
        float ai = fmaf(0.5f, tanh_approx(ci), 0.5f);
        float tu = tanh_approx(cu);
        float ao = fmaf(0.5f, tanh_approx(co), 0.5f);

        c    = fmaf(af, c, ai * tu);
        hnew = ao * tanh_approx(c);

        // broadcast h within the 8-lane group, pack duplicated for f32x2 dots
        #pragma unroll
        for (int j = 0; j < 8; j++) {
            float hj = __shfl_sync(FULL, hnew, j, 8);
            h2[j] = pack2(hj, hj);
        }

        sp[(size_t)t * (BATCH * HDIM)] = hnew;    // 128B/warp, fully coalesced
        z2 = zn;
    }

    hx_out[(size_t)b * HDIM + q] = hnew;
    cx_out[(size_t)b * HDIM + q] = c;
}

extern "C" void kernel_launch(void* const* d_in, const int* in_sizes, int n_in,
                              void* d_out, int out_size) {
    const float* inputs = (const float*)d_in[0];
    const float* Wf = (const float*)d_in[1];  const float* bf = (const float*)d_in[2];
    const float* Wi = (const float*)d_in[3];  const float* bi = (const float*)d_in[4];
    const float* Wu = (const float*)d_in[5];  const float* bu = (const float*)d_in[6];
    const float* Wo = (const float*)d_in[7];  const float* bo = (const float*)d_in[8];
    const float* pf  = (const float*)d_in[9];
    const float* pi_ = (const float*)d_in[10];
    const float* pu  = (const float*)d_in[11];
    const float* po  = (const float*)d_in[12];
    float* out = (float*)d_out;

    cudaFuncSetAttribute(qlstm_gemm, cudaFuncAttributeMaxDynamicSharedMemorySize,
                         GEMM_SMEM_BYTES);

    qlstm_gemm<<<1024, 256, GEMM_SMEM_BYTES>>>(inputs, Wf, bf, Wi, bi, Wu, bu, Wo, bo);
    qlstm_recur<<<128, 32>>>(Wf, Wi, Wu, Wo, pf, pi_, pu, po, out);
}

// round 6
// speedup vs baseline: 1.1934x; 1.1934x over previous
#include <cuda_runtime.h>
#include <cstdint>

#define SEQ     256
#define BATCH   512
#define IN_DIM  256
#define HDIM    8
#define DIN     264          // IN_DIM + HDIM
#define NROWS   (SEQ * BATCH)

// Scratch: pre-activations, bias folded in.
// Layout: zx[(t*BATCH + b)*32 + (g*8 + q)]  (column = lane in both kernels)
// Padded by one t-row so the recur prefetch never reads OOB.
__device__ __align__(16) float g_zx[(size_t)(NROWS + BATCH) * 32];

typedef unsigned long long ull;

__device__ __forceinline__ void ffma2(ull &d, ull a, ull b) {
    asm("fma.rn.f32x2 %0, %1, %2, %0;" : "+l"(d) : "l"(a), "l"(b));
}
__device__ __forceinline__ float tanh_approx(float x) {
    float y; asm("tanh.approx.f32 %0, %1;" : "=f"(y) : "f"(x)); return y;
}
__device__ __forceinline__ void cpasync16(void* dst, const void* src) {
    unsigned ds = (unsigned)__cvta_generic_to_shared(dst);
    asm volatile("cp.async.cg.shared.global [%0], [%1], 16;" :: "r"(ds), "l"(src));
}
__device__ __forceinline__ void cp_commit() { asm volatile("cp.async.commit_group;"); }
template <int N> __device__ __forceinline__ void cp_wait() {
    asm volatile("cp.async.wait_group %0;" :: "n"(N));
}

// ---------------------------------------------------------------------------
// Kernel A (round-3 version, measured ~53us): zx = x @ Wx.T + b.
// Block 256 thr, 128 rows, grid 1024. lane = output o; warp owns 16 rows.
// x tile in smem read as full-warp-broadcast LDS.128; weights swizzled in
// smem, pulled per-chunk into registers. Packed fma.rn.f32x2 accumulators.
// ---------------------------------------------------------------------------
#define KCH    32
#define NCHUNK 8

__global__ void __launch_bounds__(256)
qlstm_gemm(const float* __restrict__ x,
           const float* __restrict__ Wf, const float* __restrict__ bf,
           const float* __restrict__ Wi, const float* __restrict__ bi,
           const float* __restrict__ Wu, const float* __restrict__ bu,
           const float* __restrict__ Wo, const float* __restrict__ bo)
{
    __shared__ __align__(16) float w_s[32 * 256];      // 32KB, 16B-slot swizzled
    __shared__ __align__(16) float xs[2][128 * 32];    // 2 x 16KB x tile

    const int tid  = threadIdx.x;
    const int lane = tid & 31, warp = tid >> 5;
    const int row0   = blockIdx.x * 128;
    const int wrow0  = warp * 16;

    // Stage W x-part: 32 rows x 64 slots(16B) = 2048 slots, 8 per thread.
    #pragma unroll
    for (int i = 0; i < 8; i++) {
        int idx = tid + 256 * i;
        int o = idx >> 6, s = idx & 63;
        int sw = (s & ~7) | ((s & 7) ^ (o & 7));     // swizzle within 8-slot groups
        int g = o >> 3, q = o & 7;
        const float* base = (g == 0 ? Wf : (g == 1 ? Wi : (g == 2 ? Wu : Wo)));
        cpasync16(&w_s[o * 256 + sw * 4], base + q * DIN + s * 4);
    }

    auto load_x = [&](int kc, int buf) {
        #pragma unroll
        for (int i = 0; i < 4; i++) {
            int idx = tid + 256 * i;
            int r = idx >> 3, s = idx & 7;
            cpasync16(&xs[buf][r * 32 + s * 4],
                      x + (size_t)(row0 + r) * IN_DIM + kc * KCH + s * 4);
        }
    };

    load_x(0, 0);
    cp_commit();                     // group: {W, x-chunk0}

    ull acc[16];
    #pragma unroll
    for (int r = 0; r < 16; r++) acc[r] = 0ULL;

    #pragma unroll 1
    for (int kc = 0; kc < NCHUNK; kc++) {
        if (kc < NCHUNK - 1) { load_x(kc + 1, (kc + 1) & 1); cp_commit(); }
        if (kc < NCHUNK - 1) cp_wait<1>(); else cp_wait<0>();
        __syncthreads();

        // Pull this lane's weight chunk (32 floats) into registers.
        ull wreg[16];
        #pragma unroll
        for (int j = 0; j < 8; j++) {
            int s  = kc * 8 + j;
            int sw = (s & ~7) | ((s & 7) ^ (lane & 7));
            ulonglong2 wv = *reinterpret_cast<const ulonglong2*>(&w_s[lane * 256 + sw * 4]);
            wreg[2 * j] = wv.x; wreg[2 * j + 1] = wv.y;
        }

        const float* xb = xs[kc & 1];
        #pragma unroll
        for (int r = 0; r < 16; r++) {
            const ulonglong2* xp = reinterpret_cast<const ulonglong2*>(xb + (wrow0 + r) * 32);
            #pragma unroll
            for (int j = 0; j < 8; j++) {
                ulonglong2 xv = xp[j];                 // full-warp broadcast
                ffma2(acc[r], xv.x, wreg[2 * j]);
                ffma2(acc[r], xv.y, wreg[2 * j + 1]);
            }
        }
        __syncthreads();
    }

    const int g = lane >> 3, q = lane & 7;
    const float bias = (g == 0 ? bf : (g == 1 ? bi : (g == 2 ? bu : bo)))[q];

    #pragma unroll
    for (int r = 0; r < 16; r++) {
        float2 p = *reinterpret_cast<float2*>(&acc[r]);
        g_zx[(size_t)(row0 + wrow0 + r) * 32 + lane] = p.x + p.y + bias; // coalesced
    }
}

// ---------------------------------------------------------------------------
// Kernel B: recurrence, ZERO shuffles. One warp per batch element (512 warps),
// lane = (g, q). All cross-lane exchange through a warp-private smem strip:
//   round 1: STS cos-value -> LDS my gate's 8-vector -> masked product tree
//   round 2: STS activation at [q*4+g] -> LDS.128 (f,i,u,o) for my qubit
//   round 3: STS hnew at [q] -> LDS h 8-vector (broadcast)
// Each round = STS + WARPSYNC + LDS (~55 cyc) vs chained SHFLs (~30+/shfl,
// serialized per warp on MIO — the round-3/5 bottleneck).
// Sigmoid's 0.5x is folded into the q==0 cos prefactor for gates f,i,o.
// ---------------------------------------------------------------------------
__global__ void __launch_bounds__(128)
qlstm_recur(const float* __restrict__ Wf, const float* __restrict__ Wi,
            const float* __restrict__ Wu, const float* __restrict__ Wo,
            const float* __restrict__ pf, const float* __restrict__ pi_,
            const float* __restrict__ pu, const float* __restrict__ po,
            float* __restrict__ out)
{
    __shared__ __align__(16) float ex[4][80];   // per-warp: cv[32] a[32] h[8]+pad

    const int lane = threadIdx.x & 31;
    const int wid  = threadIdx.x >> 5;
    const int b    = blockIdx.x * 4 + wid;
    const int g = lane >> 3, q = lane & 7;

    float* cvrow = &ex[wid][0];
    float* arow  = &ex[wid][32];
    float* hrow  = &ex[wid][64];

    const float* W = (g == 0 ? Wf : (g == 1 ? Wi : (g == 2 ? Wu : Wo))) + q * DIN + IN_DIM;
    const float* p = (g == 0 ? pf : (g == 1 ? pi_ : (g == 2 ? pu : po)));

    float Whr[8];
    #pragma unroll
    for (int j = 0; j < 8; j++) Whr[j] = W[j];

    float cth = __cosf(p[q]);
    if (g != 2 && q == 0) cth *= 0.5f;          // sigmoid 0.5x folded into prefix
    const float s2 = (g == 2) ? 1.f : 0.5f;     // a = s2*tanh + s3
    const float s3 = (g == 2) ? 0.f : 0.5f;

    const bool p1 = (q >= 1), p2 = (q >= 2), p3 = (q >= 3),
               p4 = (q >= 4), p5 = (q >= 5), p6 = (q >= 6), p7 = (q >= 7);

    const float* zp = g_zx + (size_t)b * 32 + lane;
    const size_t zstr = (size_t)BATCH * 32;

    float* sp     = out + (size_t)b * HDIM + q;
    float* hx_out = out + (size_t)SEQ * BATCH * HDIM;
    float* cx_out = hx_out + (size_t)BATCH * HDIM;

    float h0=0.f,h1=0.f,h2r=0.f,h3=0.f,h4=0.f,h5=0.f,h6=0.f,h7=0.f;
    float c = 0.f, hnew = 0.f;
    float zcur = zp[0];

    #pragma unroll 2
    for (int t = 0; t < SEQ; t++) {
        float zn = zp[(size_t)(t + 1) * zstr];  // padded array: always in-bounds

        // recurrent dot, tree-shaped (depth ~20 cyc)
        float s01 = fmaf(h1, Whr[1], h0 * Whr[0]);
        float s23 = fmaf(h3, Whr[3], h2r * Whr[2]);
        float s45 = fmaf(h5, Whr[5], h4 * Whr[4]);
        float s67 = fmaf(h7, Whr[7], h6 * Whr[6]);
        float z = zcur + ((s01 + s23) + (s45 + s67));

        float cv = __cosf(z) * cth;

        // round 1: share cos values within gate group
        cvrow[lane] = cv;
        __syncwarp();
        float4 va = *reinterpret_cast<const float4*>(cvrow + g * 8);
        float4 vb = *reinterpret_cast<const float4*>(cvrow + g * 8 + 4);

        float u1 = p1 ? va.y : 1.f, u2 = p2 ? va.z : 1.f, u3 = p3 ? va.w : 1.f;
        float u4 = p4 ? vb.x : 1.f, u5 = p5 ? vb.y : 1.f, u6 = p6 ? vb.z : 1.f;
        float u7 = p7 ? vb.w : 1.f;
        float pr = ((va.x * u1) * (u2 * u3)) * ((u4 * u5) * (u6 * u7));

        float th = tanh_approx(pr);
        float a  = fmaf(s2, th, s3);

        // round 2: gather (f,i,u,o) for my qubit in one LDS.128
        arow[q * 4 + g] = a;
        __syncwarp();
        float4 fiuo = *reinterpret_cast<const float4*>(arow + q * 4);

        c    = fmaf(fiuo.x, c, fiuo.y * fiuo.z);
        hnew = fiuo.w * tanh_approx(c);

        // round 3: broadcast h vector (duplicate same-value stores are fine)
        hrow[q] = hnew;
        __syncwarp();
        float4 ha = *reinterpret_cast<const float4*>(hrow);
        float4 hb = *reinterpret_cast<const float4*>(hrow + 4);
        h0 = ha.x; h1 = ha.y; h2r = ha.z; h3 = ha.w;
        h4 = hb.x; h5 = hb.y; h6 = hb.z; h7 = hb.w;

        sp[(size_t)t * (BATCH * HDIM)] = hnew;  // 4x same-addr dup, same value
        zcur = zn;
    }

    hx_out[(size_t)b * HDIM + q] = hnew;
    cx_out[(size_t)b * HDIM + q] = c;
}

extern "C" void kernel_launch(void* const* d_in, const int* in_sizes, int n_in,
                              void* d_out, int out_size) {
    const float* inputs = (const float*)d_in[0];
    const float* Wf = (const float*)d_in[1];  const float* bf = (const float*)d_in[2];
    const float* Wi = (const float*)d_in[3];  const float* bi = (const float*)d_in[4];
    const float* Wu = (const float*)d_in[5];  const float* bu = (const float*)d_in[6];
    const float* Wo = (const float*)d_in[7];  const float* bo = (const float*)d_in[8];
    const float* pf  = (const float*)d_in[9];
    const float* pi_ = (const float*)d_in[10];
    const float* pu  = (const float*)d_in[11];
    const float* po  = (const float*)d_in[12];
    float* out = (float*)d_out;

    qlstm_gemm<<<1024, 256>>>(inputs, Wf, bf, Wi, bi, Wu, bu, Wo, bo);
    qlstm_recur<<<128, 128>>>(Wf, Wi, Wu, Wo, pf, pi_, pu, po, out);
}